// round 9
// baseline (speedup 1.0000x reference)
#include <cuda_runtime.h>
#include <cstdint>

#define T_LEN   1000000
#define HIDDEN  75
#define NS      16

#define CH      256                       // steps per pipeline chunk
#define NBUF    4                         // ring depth (power of 2)
#define NCHUNK  ((T_LEN + CH - 1) / CH)   // 3907 (last chunk = 64 steps, /8 ok)

// Shared layout: c ring | q ring | flags
#define C_RING_BYTES (NBUF * CH * 64)     // 16 floats/step
#define Q_RING_BYTES (NBUF * CH * 32)     // 8 floats/step
#define SMEM_BYTES   (C_RING_BYTES + Q_RING_BYTES + 256)

typedef unsigned long long ull;

// Scratch (no allocations allowed)
__device__ float g_cneg[T_LEN * NS];   // -log_softmax priors   (64 MB)
__device__ float g_q[T_LEN * 8];       // pre-update metrics    (32 MB)

// ---------------------------------------------------------------------------
// helpers
// ---------------------------------------------------------------------------
__device__ __forceinline__ unsigned smem_u32(const void* p) {
    return (unsigned)__cvta_generic_to_shared(p);
}
// two independent IEEE fp32 RN adds per instr (Blackwell packed f32x2)
__device__ __forceinline__ ull addx2(ull a, ull b) {
    ull r; asm("add.rn.f32x2 %0,%1,%2;" : "=l"(r) : "l"(a), "l"(b)); return r;
}
// (min(a.lo,a.hi), min(b.lo,b.hi))
__device__ __forceinline__ ull minpair(ull a, ull b) {
    ull r;
    asm("{\n\t.reg .f32 al,ah,bl,bh,rl,rh;\n\t"
        "mov.b64 {al,ah},%1;\n\t"
        "mov.b64 {bl,bh},%2;\n\t"
        "min.f32 rl,al,ah;\n\t"
        "min.f32 rh,bl,bh;\n\t"
        "mov.b64 %0,{rl,rh};\n\t}"
        : "=l"(r) : "l"(a), "l"(b));
    return r;
}
__device__ __forceinline__ void lds128(ull& a, ull& b, unsigned addr) {
    asm volatile("ld.shared.v2.u64 {%0,%1},[%2];" : "=l"(a), "=l"(b) : "r"(addr));
}
__device__ __forceinline__ void sts64(unsigned addr, ull v) {
    asm volatile("st.shared.u64 [%0],%1;" :: "r"(addr), "l"(v));
}
__device__ __forceinline__ float lof(ull v) { return __uint_as_float((unsigned)v); }
__device__ __forceinline__ float hif(ull v) { return __uint_as_float((unsigned)(v >> 32)); }

// ---------------------------------------------------------------------------
// K1: priors. Mirrors the jax fp32 pipeline (unchanged, proven).
// ---------------------------------------------------------------------------
__global__ __launch_bounds__(256)
void priors_kernel(const float* __restrict__ rx,
                   const float* __restrict__ W1,
                   const float* __restrict__ b1,
                   const float* __restrict__ W2,
                   const float* __restrict__ b2)
{
    __shared__ float  sW1[HIDDEN];
    __shared__ float  sb1[HIDDEN];
    __shared__ float  sb2[NS];
    __shared__ float4 sW2[HIDDEN * 4];

    int tid = threadIdx.x;
    for (int i = tid; i < HIDDEN; i += blockDim.x) { sW1[i] = W1[i]; sb1[i] = b1[i]; }
    for (int i = tid; i < HIDDEN * 4; i += blockDim.x)
        sW2[i] = reinterpret_cast<const float4*>(W2)[i];
    if (tid < NS) sb2[tid] = b2[tid];
    __syncthreads();

    int t = blockIdx.x * blockDim.x + tid;
    if (t >= T_LEN) return;

    float r = rx[t];

    float acc[NS];
#pragma unroll
    for (int k = 0; k < NS; k++) acc[k] = 0.0f;

#pragma unroll 5
    for (int j = 0; j < HIDDEN; j++) {
        float h = __fadd_rn(__fmul_rn(r, sW1[j]), sb1[j]);
        h = fmaxf(h, 0.0f);
        float4 w0 = sW2[j * 4 + 0];
        float4 w1 = sW2[j * 4 + 1];
        float4 w2 = sW2[j * 4 + 2];
        float4 w3 = sW2[j * 4 + 3];
        acc[0]  = __fmaf_rn(h, w0.x, acc[0]);
        acc[1]  = __fmaf_rn(h, w0.y, acc[1]);
        acc[2]  = __fmaf_rn(h, w0.z, acc[2]);
        acc[3]  = __fmaf_rn(h, w0.w, acc[3]);
        acc[4]  = __fmaf_rn(h, w1.x, acc[4]);
        acc[5]  = __fmaf_rn(h, w1.y, acc[5]);
        acc[6]  = __fmaf_rn(h, w1.z, acc[6]);
        acc[7]  = __fmaf_rn(h, w1.w, acc[7]);
        acc[8]  = __fmaf_rn(h, w2.x, acc[8]);
        acc[9]  = __fmaf_rn(h, w2.y, acc[9]);
        acc[10] = __fmaf_rn(h, w2.z, acc[10]);
        acc[11] = __fmaf_rn(h, w2.w, acc[11]);
        acc[12] = __fmaf_rn(h, w3.x, acc[12]);
        acc[13] = __fmaf_rn(h, w3.y, acc[13]);
        acc[14] = __fmaf_rn(h, w3.z, acc[14]);
        acc[15] = __fmaf_rn(h, w3.w, acc[15]);
    }

    float logit[NS];
#pragma unroll
    for (int k = 0; k < NS; k++) logit[k] = __fadd_rn(acc[k], sb2[k]);

    float m = logit[0];
#pragma unroll
    for (int k = 1; k < NS; k++) m = fmaxf(m, logit[k]);

    float sh[NS];
    float s = 0.0f;
#pragma unroll
    for (int k = 0; k < NS; k++) {
        sh[k] = __fadd_rn(logit[k], -m);
        s = __fadd_rn(s, expf(sh[k]));
    }
    float lse = logf(s);

    float out[NS];
#pragma unroll
    for (int k = 0; k < NS; k++)
        out[k] = -__fadd_rn(sh[k], -lse);

    float4* dst = reinterpret_cast<float4*>(&g_cneg[(size_t)t * NS]);
    dst[0] = make_float4(out[0],  out[1],  out[2],  out[3]);
    dst[1] = make_float4(out[4],  out[5],  out[6],  out[7]);
    dst[2] = make_float4(out[8],  out[9],  out[10], out[11]);
    dst[3] = make_float4(out[12], out[13], out[14], out[15]);
}

// one ACS step (exact reference fp32 op order)
#define ACS_STEP(C0,C1,C2,C3,C4,C5,C6,C7)                                   \
    do {                                                                    \
        ull y0 = addx2(M0, C0);                                             \
        ull y1 = addx2(M1, C1);                                             \
        ull y2 = addx2(M2, C2);                                             \
        ull y3 = addx2(M3, C3);                                             \
        ull y4 = addx2(M0, C4);                                             \
        ull y5 = addx2(M1, C5);                                             \
        ull y6 = addx2(M2, C6);                                             \
        ull y7 = addx2(M3, C7);                                             \
        M0 = minpair(y0, y1);                                               \
        M1 = minpair(y2, y3);                                               \
        M2 = minpair(y4, y5);                                               \
        M3 = minpair(y6, y7);                                               \
    } while (0)

// prefetch step into A or B regs; record metrics; compute. offsets compile-time.
#define PAIR_BODY(CO, QO)                                                   \
    do {                                                                    \
        lds128(B0, B1, ca + (CO) +  64);                                    \
        lds128(B2, B3, ca + (CO) +  80);                                    \
        lds128(B4, B5, ca + (CO) +  96);                                    \
        lds128(B6, B7, ca + (CO) + 112);                                    \
        sts64(qa + (QO) +  0, M0);                                          \
        sts64(qa + (QO) +  8, M1);                                          \
        sts64(qa + (QO) + 16, M2);                                          \
        sts64(qa + (QO) + 24, M3);                                          \
        ACS_STEP(A0, A1, A2, A3, A4, A5, A6, A7);                           \
        lds128(A0, A1, ca + (CO) + 128);                                    \
        lds128(A2, A3, ca + (CO) + 144);                                    \
        lds128(A4, A5, ca + (CO) + 160);                                    \
        lds128(A6, A7, ca + (CO) + 176);                                    \
        sts64(qa + (QO) + 32, M0);                                          \
        sts64(qa + (QO) + 40, M1);                                          \
        sts64(qa + (QO) + 48, M2);                                          \
        sts64(qa + (QO) + 56, M3);                                          \
        ACS_STEP(B0, B1, B2, B3, B4, B5, B6, B7);                           \
    } while (0)

// ---------------------------------------------------------------------------
// K2: warp-specialized single-block pipeline, one warp per SMSP.
//   warps 0-1 (tid 0..63)  : producers, gmem -> c ring   (bar.sync 1, 64)
//   warp  2  (tid 64..95)  : flusher,   q ring -> g_q    (__syncwarp)
//   warp  3  (tid 96)      : serial ACS consumer (SMSP3, uncontended)
// ---------------------------------------------------------------------------
__global__ __launch_bounds__(128, 1)
void pipeline_kernel()
{
    extern __shared__ unsigned char dynsmem[];
    ull* c_ring = reinterpret_cast<ull*>(dynsmem);
    ull* q_ring = reinterpret_cast<ull*>(dynsmem + C_RING_BYTES);
    volatile int* flags = reinterpret_cast<volatile int*>(dynsmem + C_RING_BYTES + Q_RING_BYTES);
    volatile int* c_fill = flags;             // producer -> consumer
    volatile int* c_done = flags + NBUF;      // consumer -> producer
    volatile int* q_fill = flags + 2 * NBUF;  // consumer -> flusher
    volatile int* q_done = flags + 3 * NBUF;  // flusher  -> consumer

    int tid = threadIdx.x;
    if (tid < 4 * NBUF) flags[tid] = 0;
    __syncthreads();

    if (tid < 64) {
        // ------------------- producers: gmem -> c ring -------------------
        int p = tid;   // 0..63
        const float4* src = reinterpret_cast<const float4*>(g_cneg);
        const long total4 = (long)T_LEN * 4;
        for (int k = 0; k < NCHUNK; k++) {
            int b = k & (NBUF - 1);
            int e = k >> 2;
            if (p == 0) { while (c_done[b] < e) {} }
            asm volatile("bar.sync 1, 64;" ::: "memory");
            float4* dst = reinterpret_cast<float4*>(c_ring + (size_t)b * CH * 8);
            long base4 = (long)k * (CH * 4);
#pragma unroll
            for (int j = 0; j < 16; j++) {
                int i = p + j * 64;                       // CH*4 = 1024 float4/chunk
                if (base4 + i < total4) dst[i] = src[base4 + i];
            }
            asm volatile("bar.sync 1, 64;" ::: "memory");   // also drains STS
            if (p == 0) c_fill[b] = e + 1;
        }
    } else if (tid < 96) {
        // ------------------- flusher: q ring -> g_q (global) -------------
        int f = tid - 64;  // 0..31
        for (int k = 0; k < NCHUNK; k++) {
            int b = k & (NBUF - 1);
            int e = k >> 2;
            if (f == 0) { while (q_fill[b] < e + 1) {} }
            __syncwarp();
            const float4* qsrc = reinterpret_cast<const float4*>(q_ring + (size_t)b * CH * 4);
            float4* gdst = reinterpret_cast<float4*>(&g_q[(size_t)k * CH * 8]);
            int n4 = ((k == NCHUNK - 1) ? (T_LEN - k * CH) : CH) * 2;  // float4 count
#pragma unroll
            for (int j = 0; j < 16; j++) {
                int i = f + j * 32;
                if (i < n4) gdst[i] = qsrc[i];
            }
            __syncwarp();
            if (f == 0) q_done[b] = e + 1;
        }
    } else if (tid == 96) {
        // ------------------- consumer: the serial chain (warp 3, SMSP3) ---
        const unsigned c_base0 = smem_u32(c_ring);
        const unsigned q_base0 = smem_u32(q_ring);
        ull M0 = 0, M1 = 0, M2 = 0, M3 = 0;   // (q0,q1)(q2,q3)(q4,q5)(q6,q7)

        for (int k = 0; k < NCHUNK; k++) {
            int b = k & (NBUF - 1);
            int e = k >> 2;
            while (c_fill[b] < e + 1) {}
            while (q_done[b] < e) {}
            __threadfence_block();

            const unsigned cbase = c_base0 + (unsigned)b * (CH * 64);
            const unsigned qbase = q_base0 + (unsigned)b * (CH * 32);
            const int n = (k == NCHUNK - 1) ? (T_LEN - k * CH) : CH;   // 256 or 64

            ull A0,A1,A2,A3,A4,A5,A6,A7;
            ull B0,B1,B2,B3,B4,B5,B6,B7;
            lds128(A0, A1, cbase +  0);
            lds128(A2, A3, cbase + 16);
            lds128(A4, A5, cbase + 32);
            lds128(A6, A7, cbase + 48);

            for (int s = 0; s < n; s += 8) {
                unsigned ca = cbase + (unsigned)s * 64;
                unsigned qa = qbase + (unsigned)s * 32;
                PAIR_BODY(  0,   0);
                PAIR_BODY(128,  64);
                PAIR_BODY(256, 128);
                PAIR_BODY(384, 192);
                // final A prefetch reads <=64B past buffer end: lands in the
                // next ring buffer / q ring — allocated smem, values unused.
            }

            __threadfence_block();
            q_fill[b] = e + 1;
            c_done[b] = e + 1;
        }
    }
    // tid 97..127: exit immediately (no named barriers involved)
}

// ---------------------------------------------------------------------------
// K3: per-step outputs from stored metrics (round-3 proven, bit-identical).
// ---------------------------------------------------------------------------
__global__ __launch_bounds__(256)
void output_kernel(float* __restrict__ out)
{
    int t = blockIdx.x * blockDim.x + threadIdx.x;
    if (t >= T_LEN) return;

    const float4* qs = reinterpret_cast<const float4*>(g_q);
    float4 a = qs[2 * t + 0];
    float4 b = qs[2 * t + 1];
    float q[8] = { a.x, a.y, a.z, a.w, b.x, b.y, b.z, b.w };

    float m = q[0];
    int idx = 0;
#pragma unroll
    for (int s = 1; s < 8; s++)
        if (q[s] < m) { m = q[s]; idx = s; }   // first-index argmin

    float sum = 0.0f;
#pragma unroll
    for (int s = 0; s < 8; s++)
        sum += expf(-(q[s] - m));

    out[t]         = (float)(idx & 1);   // detected_word
    out[T_LEN + t] = 1.0f / sum;         // 2 * confidence_word (== 2/sum16)
}

// ---------------------------------------------------------------------------
// Launch. Inputs: rx[1e6], W1[75], b1[75], W2[1200], b2[16].
// Output: 2*T floats, det first then 2*conf.
// ---------------------------------------------------------------------------
extern "C" void kernel_launch(void* const* d_in, const int* in_sizes, int n_in,
                              void* d_out, int out_size)
{
    const float* rx = (const float*)d_in[0];
    const float* W1 = (const float*)d_in[1];
    const float* b1 = (const float*)d_in[2];
    const float* W2 = (const float*)d_in[3];
    const float* b2 = (const float*)d_in[4];
    float* out = (float*)d_out;

    cudaFuncSetAttribute(pipeline_kernel,
                         cudaFuncAttributeMaxDynamicSharedMemorySize, SMEM_BYTES);

    int blocks = (T_LEN + 255) / 256;
    priors_kernel<<<blocks, 256>>>(rx, W1, b1, W2, b2);
    pipeline_kernel<<<1, 128, SMEM_BYTES>>>();
    output_kernel<<<blocks, 256>>>(out);
}

// round 10
// speedup vs baseline: 1.0559x; 1.0559x over previous
#include <cuda_runtime.h>
#include <cstdint>

#define T_LEN   1000000
#define HIDDEN  75
#define NS      16

#define CH      256                       // steps per pipeline chunk
#define NBUF    4                         // ring depth (power of 2)
#define NCHUNK  ((T_LEN + CH - 1) / CH)   // 3907 (last chunk = 64 steps, /4 ok)

// Shared layout: c ring | q ring | flags
#define C_RING_BYTES (NBUF * CH * 64)     // 16 floats/step
#define Q_RING_BYTES (NBUF * CH * 32)     // 8 floats/step
#define SMEM_BYTES   (C_RING_BYTES + Q_RING_BYTES + 256)

typedef unsigned long long ull;

// Scratch (no allocations allowed): negated log-softmax priors.
__device__ float g_cneg[T_LEN * NS];   // 64 MB

// ---------------------------------------------------------------------------
// helpers
// ---------------------------------------------------------------------------
__device__ __forceinline__ unsigned smem_u32(const void* p) {
    return (unsigned)__cvta_generic_to_shared(p);
}
// two independent IEEE fp32 RN adds per instr (Blackwell packed f32x2)
__device__ __forceinline__ ull addx2(ull a, ull b) {
    ull r; asm("add.rn.f32x2 %0,%1,%2;" : "=l"(r) : "l"(a), "l"(b)); return r;
}
// (min(a.lo,a.hi), min(b.lo,b.hi))
__device__ __forceinline__ ull minpair(ull a, ull b) {
    ull r;
    asm("{\n\t.reg .f32 al,ah,bl,bh,rl,rh;\n\t"
        "mov.b64 {al,ah},%1;\n\t"
        "mov.b64 {bl,bh},%2;\n\t"
        "min.f32 rl,al,ah;\n\t"
        "min.f32 rh,bl,bh;\n\t"
        "mov.b64 %0,{rl,rh};\n\t}"
        : "=l"(r) : "l"(a), "l"(b));
    return r;
}
__device__ __forceinline__ void lds128(ull& a, ull& b, unsigned addr) {
    asm volatile("ld.shared.v2.u64 {%0,%1},[%2];" : "=l"(a), "=l"(b) : "r"(addr));
}
__device__ __forceinline__ void sts64(unsigned addr, ull v) {
    asm volatile("st.shared.u64 [%0],%1;" :: "r"(addr), "l"(v));
}
__device__ __forceinline__ float lof(ull v) { return __uint_as_float((unsigned)v); }
__device__ __forceinline__ float hif(ull v) { return __uint_as_float((unsigned)(v >> 32)); }

// ---------------------------------------------------------------------------
// K1: priors. Mirrors the jax fp32 pipeline (unchanged, proven).
// ---------------------------------------------------------------------------
__global__ __launch_bounds__(256)
void priors_kernel(const float* __restrict__ rx,
                   const float* __restrict__ W1,
                   const float* __restrict__ b1,
                   const float* __restrict__ W2,
                   const float* __restrict__ b2)
{
    __shared__ float  sW1[HIDDEN];
    __shared__ float  sb1[HIDDEN];
    __shared__ float  sb2[NS];
    __shared__ float4 sW2[HIDDEN * 4];

    int tid = threadIdx.x;
    for (int i = tid; i < HIDDEN; i += blockDim.x) { sW1[i] = W1[i]; sb1[i] = b1[i]; }
    for (int i = tid; i < HIDDEN * 4; i += blockDim.x)
        sW2[i] = reinterpret_cast<const float4*>(W2)[i];
    if (tid < NS) sb2[tid] = b2[tid];
    __syncthreads();

    int t = blockIdx.x * blockDim.x + tid;
    if (t >= T_LEN) return;

    float r = rx[t];

    float acc[NS];
#pragma unroll
    for (int k = 0; k < NS; k++) acc[k] = 0.0f;

#pragma unroll 5
    for (int j = 0; j < HIDDEN; j++) {
        float h = __fadd_rn(__fmul_rn(r, sW1[j]), sb1[j]);
        h = fmaxf(h, 0.0f);
        float4 w0 = sW2[j * 4 + 0];
        float4 w1 = sW2[j * 4 + 1];
        float4 w2 = sW2[j * 4 + 2];
        float4 w3 = sW2[j * 4 + 3];
        acc[0]  = __fmaf_rn(h, w0.x, acc[0]);
        acc[1]  = __fmaf_rn(h, w0.y, acc[1]);
        acc[2]  = __fmaf_rn(h, w0.z, acc[2]);
        acc[3]  = __fmaf_rn(h, w0.w, acc[3]);
        acc[4]  = __fmaf_rn(h, w1.x, acc[4]);
        acc[5]  = __fmaf_rn(h, w1.y, acc[5]);
        acc[6]  = __fmaf_rn(h, w1.z, acc[6]);
        acc[7]  = __fmaf_rn(h, w1.w, acc[7]);
        acc[8]  = __fmaf_rn(h, w2.x, acc[8]);
        acc[9]  = __fmaf_rn(h, w2.y, acc[9]);
        acc[10] = __fmaf_rn(h, w2.z, acc[10]);
        acc[11] = __fmaf_rn(h, w2.w, acc[11]);
        acc[12] = __fmaf_rn(h, w3.x, acc[12]);
        acc[13] = __fmaf_rn(h, w3.y, acc[13]);
        acc[14] = __fmaf_rn(h, w3.z, acc[14]);
        acc[15] = __fmaf_rn(h, w3.w, acc[15]);
    }

    float logit[NS];
#pragma unroll
    for (int k = 0; k < NS; k++) logit[k] = __fadd_rn(acc[k], sb2[k]);

    float m = logit[0];
#pragma unroll
    for (int k = 1; k < NS; k++) m = fmaxf(m, logit[k]);

    float sh[NS];
    float s = 0.0f;
#pragma unroll
    for (int k = 0; k < NS; k++) {
        sh[k] = __fadd_rn(logit[k], -m);
        s = __fadd_rn(s, expf(sh[k]));
    }
    float lse = logf(s);

    float out[NS];
#pragma unroll
    for (int k = 0; k < NS; k++)
        out[k] = -__fadd_rn(sh[k], -lse);

    float4* dst = reinterpret_cast<float4*>(&g_cneg[(size_t)t * NS]);
    dst[0] = make_float4(out[0],  out[1],  out[2],  out[3]);
    dst[1] = make_float4(out[4],  out[5],  out[6],  out[7]);
    dst[2] = make_float4(out[8],  out[9],  out[10], out[11]);
    dst[3] = make_float4(out[12], out[13], out[14], out[15]);
}

// one ACS step (exact reference fp32 op order)
#define ACS_STEP(C0,C1,C2,C3,C4,C5,C6,C7)                                   \
    do {                                                                    \
        ull y0 = addx2(M0, C0);                                             \
        ull y1 = addx2(M1, C1);                                             \
        ull y2 = addx2(M2, C2);                                             \
        ull y3 = addx2(M3, C3);                                             \
        ull y4 = addx2(M0, C4);                                             \
        ull y5 = addx2(M1, C5);                                             \
        ull y6 = addx2(M2, C6);                                             \
        ull y7 = addx2(M3, C7);                                             \
        M0 = minpair(y0, y1);                                               \
        M1 = minpair(y2, y3);                                               \
        M2 = minpair(y4, y5);                                               \
        M3 = minpair(y6, y7);                                               \
    } while (0)

// load one step's 64B of c into set L*, record metrics, exec set E*.
// CO/QO are compile-time byte offsets from ca/qa. Prefetch distance = 2 steps.
#define STEP_BODY(L0,L1,L2,L3,L4,L5,L6,L7, E0,E1,E2,E3,E4,E5,E6,E7, CO, QO) \
    do {                                                                    \
        lds128(L0, L1, ca + (CO) +  0);                                     \
        lds128(L2, L3, ca + (CO) + 16);                                     \
        lds128(L4, L5, ca + (CO) + 32);                                     \
        lds128(L6, L7, ca + (CO) + 48);                                     \
        sts64(qa + (QO) +  0, M0);                                          \
        sts64(qa + (QO) +  8, M1);                                          \
        sts64(qa + (QO) + 16, M2);                                          \
        sts64(qa + (QO) + 24, M3);                                          \
        ACS_STEP(E0, E1, E2, E3, E4, E5, E6, E7);                           \
    } while (0)

// ---------------------------------------------------------------------------
// K2: warp-specialized single-block pipeline (round-7 structure).
//   tid 0        : serial ACS consumer, 4-deep register-rotated SW pipeline
//   tid 1..31    : exit
//   tid 32..95   : producers, gmem -> c ring     (bar.sync 1, 64)
//   tid 96..223  : drainers,  q ring -> det/conf (bar.sync 2, 128)
// ---------------------------------------------------------------------------
__global__ __launch_bounds__(224, 1)
void pipeline_kernel(float* __restrict__ out)
{
    extern __shared__ unsigned char dynsmem[];
    ull* c_ring = reinterpret_cast<ull*>(dynsmem);
    ull* q_ring = reinterpret_cast<ull*>(dynsmem + C_RING_BYTES);
    volatile int* flags = reinterpret_cast<volatile int*>(dynsmem + C_RING_BYTES + Q_RING_BYTES);
    volatile int* c_fill = flags;             // producer -> consumer
    volatile int* c_done = flags + NBUF;      // consumer -> producer
    volatile int* q_fill = flags + 2 * NBUF;  // consumer -> drainer
    volatile int* q_done = flags + 3 * NBUF;  // drainer -> consumer

    int tid = threadIdx.x;
    if (tid < 4 * NBUF) flags[tid] = 0;
    __syncthreads();

    if (tid == 0) {
        // ------------------- consumer: the serial chain -------------------
        const unsigned c_base0 = smem_u32(c_ring);
        const unsigned q_base0 = smem_u32(q_ring);
        ull M0 = 0, M1 = 0, M2 = 0, M3 = 0;   // (q0,q1)(q2,q3)(q4,q5)(q6,q7)

        ull A0,A1,A2,A3,A4,A5,A6,A7;
        ull B0,B1,B2,B3,B4,B5,B6,B7;
        ull C0,C1,C2,C3,C4,C5,C6,C7;
        ull D0,D1,D2,D3,D4,D5,D6,D7;

        for (int k = 0; k < NCHUNK; k++) {
            int b = k & (NBUF - 1);
            int e = k >> 2;                    // epoch (NBUF == 4)
            while (c_fill[b] < e + 1) {}
            while (q_done[b] < e) {}
            __threadfence_block();

            const unsigned cbase = c_base0 + (unsigned)b * (CH * 64);
            const unsigned qbase = q_base0 + (unsigned)b * (CH * 32);
            const int n = (k == NCHUNK - 1) ? (T_LEN - k * CH) : CH;   // 256 or 64

            // preload steps 0 and 1
            lds128(A0, A1, cbase +   0);
            lds128(A2, A3, cbase +  16);
            lds128(A4, A5, cbase +  32);
            lds128(A6, A7, cbase +  48);
            lds128(B0, B1, cbase +  64);
            lds128(B2, B3, cbase +  80);
            lds128(B4, B5, cbase +  96);
            lds128(B6, B7, cbase + 112);

            for (int s = 0; s < n; s += 4) {
                unsigned ca = cbase + (unsigned)s * 64;
                unsigned qa = qbase + (unsigned)s * 32;
                // load s+2 / exec s ; load s+3 / exec s+1 ; etc.
                STEP_BODY(C0,C1,C2,C3,C4,C5,C6,C7, A0,A1,A2,A3,A4,A5,A6,A7, 128,  0);
                STEP_BODY(D0,D1,D2,D3,D4,D5,D6,D7, B0,B1,B2,B3,B4,B5,B6,B7, 192, 32);
                STEP_BODY(A0,A1,A2,A3,A4,A5,A6,A7, C0,C1,C2,C3,C4,C5,C6,C7, 256, 64);
                STEP_BODY(B0,B1,B2,B3,B4,B5,B6,B7, D0,D1,D2,D3,D4,D5,D6,D7, 320, 96);
                // trailing loads read <=128B past buffer end: land in the next
                // ring buffer / q ring — allocated smem, values unused.
            }

            __threadfence_block();
            q_fill[b] = e + 1;
            c_done[b] = e + 1;
        }
    } else if (tid < 32) {
        // idle lanes of warp 0 — exit (participate in NO named barriers)
        return;
    } else if (tid < 96) {
        // ------------------- producers: gmem -> c ring -------------------
        int p = tid - 32;   // 0..63
        const float4* src = reinterpret_cast<const float4*>(g_cneg);
        const long total4 = (long)T_LEN * 4;
        for (int k = 0; k < NCHUNK; k++) {
            int b = k & (NBUF - 1);
            int e = k >> 2;
            if (p == 0) { while (c_done[b] < e) {} }
            asm volatile("bar.sync 1, 64;" ::: "memory");
            float4* dst = reinterpret_cast<float4*>(c_ring + (size_t)b * CH * 8);
            long base4 = (long)k * (CH * 4);
#pragma unroll
            for (int j = 0; j < 16; j++) {
                int i = p + j * 64;                       // CH*4 = 1024 float4/chunk
                if (base4 + i < total4) dst[i] = src[base4 + i];
            }
            asm volatile("bar.sync 1, 64;" ::: "memory");   // also drains STS
            if (p == 0) c_fill[b] = e + 1;
        }
    } else {
        // ------------------- drainers: q ring -> det/conf -> out ----------
        int d = tid - 96;  // 0..127
        for (int k = 0; k < NCHUNK; k++) {
            int b = k & (NBUF - 1);
            int e = k >> 2;
            if (d == 0) { while (q_fill[b] < e + 1) {} }
            asm volatile("bar.sync 2, 128;" ::: "memory");
            __threadfence_block();
            const ull* qb = q_ring + (size_t)b * CH * 4;
            int n = (k == NCHUNK - 1) ? (T_LEN - k * CH) : CH;
            for (int s = d; s < n; s += 128) {
                ull u0 = qb[4 * s + 0];
                ull u1 = qb[4 * s + 1];
                ull u2 = qb[4 * s + 2];
                ull u3 = qb[4 * s + 3];
                float q[8] = { lof(u0), hif(u0), lof(u1), hif(u1),
                               lof(u2), hif(u2), lof(u3), hif(u3) };
                float m = q[0];
                int idx = 0;
#pragma unroll
                for (int s2 = 1; s2 < 8; s2++)
                    if (q[s2] < m) { m = q[s2]; idx = s2; }  // first-index argmin
                float sum = 0.0f;
#pragma unroll
                for (int s2 = 0; s2 < 8; s2++)
                    sum += expf(-(q[s2] - m));
                int t = k * CH + s;
                out[t]         = (float)(idx & 1);   // detected_word
                out[T_LEN + t] = 1.0f / sum;         // 2 * confidence_word (== 2/sum16)
            }
            asm volatile("bar.sync 2, 128;" ::: "memory");
            if (d == 0) q_done[b] = e + 1;
        }
    }
}

// ---------------------------------------------------------------------------
// Launch. Inputs: rx[1e6], W1[75], b1[75], W2[1200], b2[16].
// Output: 2*T floats, det first then 2*conf.
// ---------------------------------------------------------------------------
extern "C" void kernel_launch(void* const* d_in, const int* in_sizes, int n_in,
                              void* d_out, int out_size)
{
    const float* rx = (const float*)d_in[0];
    const float* W1 = (const float*)d_in[1];
    const float* b1 = (const float*)d_in[2];
    const float* W2 = (const float*)d_in[3];
    const float* b2 = (const float*)d_in[4];
    float* out = (float*)d_out;

    cudaFuncSetAttribute(pipeline_kernel,
                         cudaFuncAttributeMaxDynamicSharedMemorySize, SMEM_BYTES);

    int blocks = (T_LEN + 255) / 256;
    priors_kernel<<<blocks, 256>>>(rx, W1, b1, W2, b2);
    pipeline_kernel<<<1, 224, SMEM_BYTES>>>(out);
}

// round 11
// speedup vs baseline: 1.2047x; 1.1409x over previous
#include <cuda_runtime.h>
#include <cstdint>

#define T_LEN   1000000
#define HIDDEN  75
#define NS      16

#define CH      256                       // steps per pipeline chunk
#define NBUF    4                         // ring depth (power of 2)
#define NCHUNK  ((T_LEN + CH - 1) / CH)   // 3907 (last chunk = 64 steps, /8 ok)

// Shared layout: c ring | q ring | flags
#define C_RING_BYTES (NBUF * CH * 64)     // 16 floats/step
#define Q_RING_BYTES (NBUF * CH * 32)     // 8 floats/step
#define SMEM_BYTES   (C_RING_BYTES + Q_RING_BYTES + 256)

typedef unsigned long long ull;

// Scratch (no allocations allowed): negated log-softmax priors.
__device__ float g_cneg[T_LEN * NS];   // 64 MB

// ---------------------------------------------------------------------------
// helpers
// ---------------------------------------------------------------------------
__device__ __forceinline__ unsigned smem_u32(const void* p) {
    return (unsigned)__cvta_generic_to_shared(p);
}
// LDS.128 into four scalar fp32 regs (vector destructure = pure renames)
__device__ __forceinline__ void lds128f(float& a, float& b, float& c, float& d,
                                        unsigned addr) {
    asm volatile("ld.shared.v4.f32 {%0,%1,%2,%3},[%4];"
                 : "=f"(a), "=f"(b), "=f"(c), "=f"(d) : "r"(addr));
}
__device__ __forceinline__ void sts128f(unsigned addr, float a, float b,
                                        float c, float d) {
    asm volatile("st.shared.v4.f32 [%0],{%1,%2,%3,%4};"
                 :: "r"(addr), "f"(a), "f"(b), "f"(c), "f"(d));
}
__device__ __forceinline__ float lof(ull v) { return __uint_as_float((unsigned)v); }
__device__ __forceinline__ float hif(ull v) { return __uint_as_float((unsigned)(v >> 32)); }

// ---------------------------------------------------------------------------
// K1: priors. Mirrors the jax fp32 pipeline (unchanged, proven).
// ---------------------------------------------------------------------------
__global__ __launch_bounds__(256)
void priors_kernel(const float* __restrict__ rx,
                   const float* __restrict__ W1,
                   const float* __restrict__ b1,
                   const float* __restrict__ W2,
                   const float* __restrict__ b2)
{
    __shared__ float  sW1[HIDDEN];
    __shared__ float  sb1[HIDDEN];
    __shared__ float  sb2[NS];
    __shared__ float4 sW2[HIDDEN * 4];

    int tid = threadIdx.x;
    for (int i = tid; i < HIDDEN; i += blockDim.x) { sW1[i] = W1[i]; sb1[i] = b1[i]; }
    for (int i = tid; i < HIDDEN * 4; i += blockDim.x)
        sW2[i] = reinterpret_cast<const float4*>(W2)[i];
    if (tid < NS) sb2[tid] = b2[tid];
    __syncthreads();

    int t = blockIdx.x * blockDim.x + tid;
    if (t >= T_LEN) return;

    float r = rx[t];

    float acc[NS];
#pragma unroll
    for (int k = 0; k < NS; k++) acc[k] = 0.0f;

#pragma unroll 5
    for (int j = 0; j < HIDDEN; j++) {
        float h = __fadd_rn(__fmul_rn(r, sW1[j]), sb1[j]);
        h = fmaxf(h, 0.0f);
        float4 w0 = sW2[j * 4 + 0];
        float4 w1 = sW2[j * 4 + 1];
        float4 w2 = sW2[j * 4 + 2];
        float4 w3 = sW2[j * 4 + 3];
        acc[0]  = __fmaf_rn(h, w0.x, acc[0]);
        acc[1]  = __fmaf_rn(h, w0.y, acc[1]);
        acc[2]  = __fmaf_rn(h, w0.z, acc[2]);
        acc[3]  = __fmaf_rn(h, w0.w, acc[3]);
        acc[4]  = __fmaf_rn(h, w1.x, acc[4]);
        acc[5]  = __fmaf_rn(h, w1.y, acc[5]);
        acc[6]  = __fmaf_rn(h, w1.z, acc[6]);
        acc[7]  = __fmaf_rn(h, w1.w, acc[7]);
        acc[8]  = __fmaf_rn(h, w2.x, acc[8]);
        acc[9]  = __fmaf_rn(h, w2.y, acc[9]);
        acc[10] = __fmaf_rn(h, w2.z, acc[10]);
        acc[11] = __fmaf_rn(h, w2.w, acc[11]);
        acc[12] = __fmaf_rn(h, w3.x, acc[12]);
        acc[13] = __fmaf_rn(h, w3.y, acc[13]);
        acc[14] = __fmaf_rn(h, w3.z, acc[14]);
        acc[15] = __fmaf_rn(h, w3.w, acc[15]);
    }

    float logit[NS];
#pragma unroll
    for (int k = 0; k < NS; k++) logit[k] = __fadd_rn(acc[k], sb2[k]);

    float m = logit[0];
#pragma unroll
    for (int k = 1; k < NS; k++) m = fmaxf(m, logit[k]);

    float sh[NS];
    float s = 0.0f;
#pragma unroll
    for (int k = 0; k < NS; k++) {
        sh[k] = __fadd_rn(logit[k], -m);
        s = __fadd_rn(s, expf(sh[k]));
    }
    float lse = logf(s);

    float out[NS];
#pragma unroll
    for (int k = 0; k < NS; k++)
        out[k] = -__fadd_rn(sh[k], -lse);

    float4* dst = reinterpret_cast<float4*>(&g_cneg[(size_t)t * NS]);
    dst[0] = make_float4(out[0],  out[1],  out[2],  out[3]);
    dst[1] = make_float4(out[4],  out[5],  out[6],  out[7]);
    dst[2] = make_float4(out[8],  out[9],  out[10], out[11]);
    dst[3] = make_float4(out[12], out[13], out[14], out[15]);
}

// One scalar ACS step (exact reference fp32 op order):
//   exec on buffer EX (16 floats), prefetch next step's c into buffer LD,
//   record pre-update metrics. CO/QO compile-time offsets from ca/qa.
#define SSTEP(EX, LD, CO, QO)                                               \
    do {                                                                    \
        lds128f(LD##0,  LD##1,  LD##2,  LD##3,  ca + (CO) +  0);            \
        lds128f(LD##4,  LD##5,  LD##6,  LD##7,  ca + (CO) + 16);            \
        lds128f(LD##8,  LD##9,  LD##10, LD##11, ca + (CO) + 32);            \
        lds128f(LD##12, LD##13, LD##14, LD##15, ca + (CO) + 48);            \
        sts128f(qa + (QO) +  0, q0, q1, q2, q3);                            \
        sts128f(qa + (QO) + 16, q4, q5, q6, q7);                            \
        float x0  = __fadd_rn(q0, EX##0);                                   \
        float x1  = __fadd_rn(q1, EX##1);                                   \
        float x2  = __fadd_rn(q2, EX##2);                                   \
        float x3  = __fadd_rn(q3, EX##3);                                   \
        float x4  = __fadd_rn(q4, EX##4);                                   \
        float x5  = __fadd_rn(q5, EX##5);                                   \
        float x6  = __fadd_rn(q6, EX##6);                                   \
        float x7  = __fadd_rn(q7, EX##7);                                   \
        float x8  = __fadd_rn(q0, EX##8);                                   \
        float x9  = __fadd_rn(q1, EX##9);                                   \
        float x10 = __fadd_rn(q2, EX##10);                                  \
        float x11 = __fadd_rn(q3, EX##11);                                  \
        float x12 = __fadd_rn(q4, EX##12);                                  \
        float x13 = __fadd_rn(q5, EX##13);                                  \
        float x14 = __fadd_rn(q6, EX##14);                                  \
        float x15 = __fadd_rn(q7, EX##15);                                  \
        q0 = fminf(x0,  x1);                                                \
        q1 = fminf(x2,  x3);                                                \
        q2 = fminf(x4,  x5);                                                \
        q3 = fminf(x6,  x7);                                                \
        q4 = fminf(x8,  x9);                                                \
        q5 = fminf(x10, x11);                                               \
        q6 = fminf(x12, x13);                                               \
        q7 = fminf(x14, x15);                                               \
    } while (0)

// ---------------------------------------------------------------------------
// K2: warp-specialized single-block pipeline (round-7/10 proven structure).
//   tid 0        : serial scalar ACS consumer (A/B rotation, 8-step unroll)
//   tid 1..31    : exit
//   tid 32..95   : producers, gmem -> c ring     (bar.sync 1, 64)
//   tid 96..223  : drainers,  q ring -> det/conf (bar.sync 2, 128)
// ---------------------------------------------------------------------------
__global__ __launch_bounds__(224, 1)
void pipeline_kernel(float* __restrict__ out)
{
    extern __shared__ unsigned char dynsmem[];
    ull* c_ring = reinterpret_cast<ull*>(dynsmem);
    ull* q_ring = reinterpret_cast<ull*>(dynsmem + C_RING_BYTES);
    volatile int* flags = reinterpret_cast<volatile int*>(dynsmem + C_RING_BYTES + Q_RING_BYTES);
    volatile int* c_fill = flags;             // producer -> consumer
    volatile int* c_done = flags + NBUF;      // consumer -> producer
    volatile int* q_fill = flags + 2 * NBUF;  // consumer -> drainer
    volatile int* q_done = flags + 3 * NBUF;  // drainer -> consumer

    int tid = threadIdx.x;
    if (tid < 4 * NBUF) flags[tid] = 0;
    __syncthreads();

    if (tid == 0) {
        // ------------------- consumer: the serial chain -------------------
        const unsigned c_base0 = smem_u32(c_ring);
        const unsigned q_base0 = smem_u32(q_ring);
        float q0 = 0.f, q1 = 0.f, q2 = 0.f, q3 = 0.f;
        float q4 = 0.f, q5 = 0.f, q6 = 0.f, q7 = 0.f;

        float a0,a1,a2,a3,a4,a5,a6,a7,a8,a9,a10,a11,a12,a13,a14,a15;
        float b0,b1,b2,b3,b4,b5,b6,b7,b8,b9,b10,b11,b12,b13,b14,b15;

        for (int k = 0; k < NCHUNK; k++) {
            int b = k & (NBUF - 1);
            int e = k >> 2;                    // epoch (NBUF == 4)
            while (c_fill[b] < e + 1) {}
            while (q_done[b] < e) {}
            __threadfence_block();

            const unsigned cbase = c_base0 + (unsigned)b * (CH * 64);
            const unsigned qbase = q_base0 + (unsigned)b * (CH * 32);
            const int n = (k == NCHUNK - 1) ? (T_LEN - k * CH) : CH;   // 256 or 64

            // preload step 0 into A
            lds128f(a0,  a1,  a2,  a3,  cbase +  0);
            lds128f(a4,  a5,  a6,  a7,  cbase + 16);
            lds128f(a8,  a9,  a10, a11, cbase + 32);
            lds128f(a12, a13, a14, a15, cbase + 48);

            for (int s = 0; s < n; s += 8) {
                unsigned ca = cbase + (unsigned)s * 64;
                unsigned qa = qbase + (unsigned)s * 32;
                SSTEP(a, b,  64,   0);   // exec s,   load s+1
                SSTEP(b, a, 128,  32);   // exec s+1, load s+2
                SSTEP(a, b, 192,  64);
                SSTEP(b, a, 256,  96);
                SSTEP(a, b, 320, 128);
                SSTEP(b, a, 384, 160);
                SSTEP(a, b, 448, 192);
                SSTEP(b, a, 512, 224);   // loads s+8 -> next iteration's A
                // trailing load reads <=64B past buffer end: lands in the
                // next ring buffer / q ring — allocated smem, values unused.
            }

            __threadfence_block();
            q_fill[b] = e + 1;
            c_done[b] = e + 1;
        }
    } else if (tid < 32) {
        // idle lanes of warp 0 — exit (participate in NO named barriers)
        return;
    } else if (tid < 96) {
        // ------------------- producers: gmem -> c ring -------------------
        int p = tid - 32;   // 0..63
        const float4* src = reinterpret_cast<const float4*>(g_cneg);
        const long total4 = (long)T_LEN * 4;
        for (int k = 0; k < NCHUNK; k++) {
            int b = k & (NBUF - 1);
            int e = k >> 2;
            if (p == 0) { while (c_done[b] < e) {} }
            asm volatile("bar.sync 1, 64;" ::: "memory");
            float4* dst = reinterpret_cast<float4*>(c_ring + (size_t)b * CH * 8);
            long base4 = (long)k * (CH * 4);
#pragma unroll
            for (int j = 0; j < 16; j++) {
                int i = p + j * 64;                       // CH*4 = 1024 float4/chunk
                if (base4 + i < total4) dst[i] = src[base4 + i];
            }
            asm volatile("bar.sync 1, 64;" ::: "memory");   // also drains STS
            if (p == 0) c_fill[b] = e + 1;
        }
    } else {
        // ------------------- drainers: q ring -> det/conf -> out ----------
        int d = tid - 96;  // 0..127
        for (int k = 0; k < NCHUNK; k++) {
            int b = k & (NBUF - 1);
            int e = k >> 2;
            if (d == 0) { while (q_fill[b] < e + 1) {} }
            asm volatile("bar.sync 2, 128;" ::: "memory");
            __threadfence_block();
            const ull* qb = q_ring + (size_t)b * CH * 4;
            int n = (k == NCHUNK - 1) ? (T_LEN - k * CH) : CH;
            for (int s = d; s < n; s += 128) {
                ull u0 = qb[4 * s + 0];
                ull u1 = qb[4 * s + 1];
                ull u2 = qb[4 * s + 2];
                ull u3 = qb[4 * s + 3];
                float q[8] = { lof(u0), hif(u0), lof(u1), hif(u1),
                               lof(u2), hif(u2), lof(u3), hif(u3) };
                float m = q[0];
                int idx = 0;
#pragma unroll
                for (int s2 = 1; s2 < 8; s2++)
                    if (q[s2] < m) { m = q[s2]; idx = s2; }  // first-index argmin
                float sum = 0.0f;
#pragma unroll
                for (int s2 = 0; s2 < 8; s2++)
                    sum += expf(-(q[s2] - m));
                int t = k * CH + s;
                out[t]         = (float)(idx & 1);   // detected_word
                out[T_LEN + t] = 1.0f / sum;         // 2 * confidence_word (== 2/sum16)
            }
            asm volatile("bar.sync 2, 128;" ::: "memory");
            if (d == 0) q_done[b] = e + 1;
        }
    }
}

// ---------------------------------------------------------------------------
// Launch. Inputs: rx[1e6], W1[75], b1[75], W2[1200], b2[16].
// Output: 2*T floats, det first then 2*conf.
// ---------------------------------------------------------------------------
extern "C" void kernel_launch(void* const* d_in, const int* in_sizes, int n_in,
                              void* d_out, int out_size)
{
    const float* rx = (const float*)d_in[0];
    const float* W1 = (const float*)d_in[1];
    const float* b1 = (const float*)d_in[2];
    const float* W2 = (const float*)d_in[3];
    const float* b2 = (const float*)d_in[4];
    float* out = (float*)d_out;

    cudaFuncSetAttribute(pipeline_kernel,
                         cudaFuncAttributeMaxDynamicSharedMemorySize, SMEM_BYTES);

    int blocks = (T_LEN + 255) / 256;
    priors_kernel<<<blocks, 256>>>(rx, W1, b1, W2, b2);
    pipeline_kernel<<<1, 224, SMEM_BYTES>>>(out);
}

// round 13
// speedup vs baseline: 1.3046x; 1.0829x over previous
#include <cuda_runtime.h>
#include <cstdint>

#define T_LEN   1000000
#define HIDDEN  75
#define NS      16

#define CH      256                       // steps per pipeline chunk
#define NBUF    4                         // ring depth (power of 2)
#define NCHUNK  ((T_LEN + CH - 1) / CH)   // 3907 (last chunk = 64 steps, /8 ok)

// Shared layout: c ring | q ring | flags
#define C_RING_BYTES (NBUF * CH * 64)     // 16 floats/step
#define Q_RING_BYTES (NBUF * CH * 32)     // 8 floats/step
#define SMEM_BYTES   (C_RING_BYTES + Q_RING_BYTES + 256)

typedef unsigned long long ull;

// Scratch (no allocations allowed): negated log-softmax priors.
__device__ float g_cneg[T_LEN * NS];   // 64 MB

// ---------------------------------------------------------------------------
// helpers
// ---------------------------------------------------------------------------
__device__ __forceinline__ unsigned smem_u32(const void* p) {
    return (unsigned)__cvta_generic_to_shared(p);
}
// LDS.128 into four scalar fp32 regs (vector destructure = pure renames)
__device__ __forceinline__ void lds128f(float& a, float& b, float& c, float& d,
                                        unsigned addr) {
    asm volatile("ld.shared.v4.f32 {%0,%1,%2,%3},[%4];"
                 : "=f"(a), "=f"(b), "=f"(c), "=f"(d) : "r"(addr));
}
__device__ __forceinline__ void sts128f(unsigned addr, float a, float b,
                                        float c, float d) {
    asm volatile("st.shared.v4.f32 [%0],{%1,%2,%3,%4};"
                 :: "r"(addr), "f"(a), "f"(b), "f"(c), "f"(d));
}
// (xo0,xo1) = (qa+ca, qb+cb) as ONE packed f32x2 add on the fma pipe.
// Scalar float operands; mov.b64 pack/destructure lower to reg-alloc
// constraints (renames), not copies.
__device__ __forceinline__ void addx2f(float& xo0, float& xo1,
                                       float qa, float qb, float ca, float cb) {
    asm("{\n\t.reg .b64 u,v,w;\n\t"
        "mov.b64 u,{%2,%3};\n\t"
        "mov.b64 v,{%4,%5};\n\t"
        "add.rn.f32x2 w,u,v;\n\t"
        "mov.b64 {%0,%1},w;\n\t}"
        : "=f"(xo0), "=f"(xo1)
        : "f"(qa), "f"(qb), "f"(ca), "f"(cb));
}
__device__ __forceinline__ float lof(ull v) { return __uint_as_float((unsigned)v); }
__device__ __forceinline__ float hif(ull v) { return __uint_as_float((unsigned)(v >> 32)); }

// ---------------------------------------------------------------------------
// K1: priors. Mirrors the jax fp32 pipeline (unchanged, proven).
// ---------------------------------------------------------------------------
__global__ __launch_bounds__(256)
void priors_kernel(const float* __restrict__ rx,
                   const float* __restrict__ W1,
                   const float* __restrict__ b1,
                   const float* __restrict__ W2,
                   const float* __restrict__ b2)
{
    __shared__ float  sW1[HIDDEN];
    __shared__ float  sb1[HIDDEN];
    __shared__ float  sb2[NS];
    __shared__ float4 sW2[HIDDEN * 4];

    int tid = threadIdx.x;
    for (int i = tid; i < HIDDEN; i += blockDim.x) { sW1[i] = W1[i]; sb1[i] = b1[i]; }
    for (int i = tid; i < HIDDEN * 4; i += blockDim.x)
        sW2[i] = reinterpret_cast<const float4*>(W2)[i];
    if (tid < NS) sb2[tid] = b2[tid];
    __syncthreads();

    int t = blockIdx.x * blockDim.x + tid;
    if (t >= T_LEN) return;

    float r = rx[t];

    float acc[NS];
#pragma unroll
    for (int k = 0; k < NS; k++) acc[k] = 0.0f;

#pragma unroll 5
    for (int j = 0; j < HIDDEN; j++) {
        float h = __fadd_rn(__fmul_rn(r, sW1[j]), sb1[j]);
        h = fmaxf(h, 0.0f);
        float4 w0 = sW2[j * 4 + 0];
        float4 w1 = sW2[j * 4 + 1];
        float4 w2 = sW2[j * 4 + 2];
        float4 w3 = sW2[j * 4 + 3];
        acc[0]  = __fmaf_rn(h, w0.x, acc[0]);
        acc[1]  = __fmaf_rn(h, w0.y, acc[1]);
        acc[2]  = __fmaf_rn(h, w0.z, acc[2]);
        acc[3]  = __fmaf_rn(h, w0.w, acc[3]);
        acc[4]  = __fmaf_rn(h, w1.x, acc[4]);
        acc[5]  = __fmaf_rn(h, w1.y, acc[5]);
        acc[6]  = __fmaf_rn(h, w1.z, acc[6]);
        acc[7]  = __fmaf_rn(h, w1.w, acc[7]);
        acc[8]  = __fmaf_rn(h, w2.x, acc[8]);
        acc[9]  = __fmaf_rn(h, w2.y, acc[9]);
        acc[10] = __fmaf_rn(h, w2.z, acc[10]);
        acc[11] = __fmaf_rn(h, w2.w, acc[11]);
        acc[12] = __fmaf_rn(h, w3.x, acc[12]);
        acc[13] = __fmaf_rn(h, w3.y, acc[13]);
        acc[14] = __fmaf_rn(h, w3.z, acc[14]);
        acc[15] = __fmaf_rn(h, w3.w, acc[15]);
    }

    float logit[NS];
#pragma unroll
    for (int k = 0; k < NS; k++) logit[k] = __fadd_rn(acc[k], sb2[k]);

    float m = logit[0];
#pragma unroll
    for (int k = 1; k < NS; k++) m = fmaxf(m, logit[k]);

    float sh[NS];
    float s = 0.0f;
#pragma unroll
    for (int k = 0; k < NS; k++) {
        sh[k] = __fadd_rn(logit[k], -m);
        s = __fadd_rn(s, expf(sh[k]));
    }
    float lse = logf(s);

    float out[NS];
#pragma unroll
    for (int k = 0; k < NS; k++)
        out[k] = -__fadd_rn(sh[k], -lse);

    float4* dst = reinterpret_cast<float4*>(&g_cneg[(size_t)t * NS]);
    dst[0] = make_float4(out[0],  out[1],  out[2],  out[3]);
    dst[1] = make_float4(out[4],  out[5],  out[6],  out[7]);
    dst[2] = make_float4(out[8],  out[9],  out[10], out[11]);
    dst[3] = make_float4(out[12], out[13], out[14], out[15]);
}

// One ACS step (exact reference fp32 op order): 8 packed f32x2 adds replace
// 16 scalar FADDs (halves the fma-pipe span); mins stay scalar FMNMX that
// source the packed halves directly (no unpack needed at SASS level).
#define SSTEP(EX, LD, CO, QO)                                               \
    do {                                                                    \
        lds128f(LD##0,  LD##1,  LD##2,  LD##3,  ca + (CO) +  0);            \
        lds128f(LD##4,  LD##5,  LD##6,  LD##7,  ca + (CO) + 16);            \
        lds128f(LD##8,  LD##9,  LD##10, LD##11, ca + (CO) + 32);            \
        lds128f(LD##12, LD##13, LD##14, LD##15, ca + (CO) + 48);            \
        sts128f(qa + (QO) +  0, q0, q1, q2, q3);                            \
        sts128f(qa + (QO) + 16, q4, q5, q6, q7);                            \
        float x0,x1,x2,x3,x4,x5,x6,x7,x8,x9,x10,x11,x12,x13,x14,x15;        \
        addx2f(x0,  x1,  q0, q1, EX##0,  EX##1);                            \
        addx2f(x2,  x3,  q2, q3, EX##2,  EX##3);                            \
        addx2f(x4,  x5,  q4, q5, EX##4,  EX##5);                            \
        addx2f(x6,  x7,  q6, q7, EX##6,  EX##7);                            \
        addx2f(x8,  x9,  q0, q1, EX##8,  EX##9);                            \
        addx2f(x10, x11, q2, q3, EX##10, EX##11);                           \
        addx2f(x12, x13, q4, q5, EX##12, EX##13);                           \
        addx2f(x14, x15, q6, q7, EX##14, EX##15);                           \
        q0 = fminf(x0,  x1);                                                \
        q1 = fminf(x2,  x3);                                                \
        q2 = fminf(x4,  x5);                                                \
        q3 = fminf(x6,  x7);                                                \
        q4 = fminf(x8,  x9);                                                \
        q5 = fminf(x10, x11);                                               \
        q6 = fminf(x12, x13);                                               \
        q7 = fminf(x14, x15);                                               \
    } while (0)

// ---------------------------------------------------------------------------
// K2: warp-specialized single-block pipeline (proven structure).
//   tid 0        : serial ACS consumer (A/B rotation, 8-step unroll)
//   tid 1..31    : exit
//   tid 32..95   : producers, gmem -> c ring     (bar.sync 1, 64)
//   tid 96..223  : drainers,  q ring -> det/conf (bar.sync 2, 128)
// ---------------------------------------------------------------------------
__global__ __launch_bounds__(224, 1)
void pipeline_kernel(float* __restrict__ out)
{
    extern __shared__ unsigned char dynsmem[];
    ull* c_ring = reinterpret_cast<ull*>(dynsmem);
    ull* q_ring = reinterpret_cast<ull*>(dynsmem + C_RING_BYTES);
    volatile int* flags = reinterpret_cast<volatile int*>(dynsmem + C_RING_BYTES + Q_RING_BYTES);
    volatile int* c_fill = flags;             // producer -> consumer
    volatile int* c_done = flags + NBUF;      // consumer -> producer
    volatile int* q_fill = flags + 2 * NBUF;  // consumer -> drainer
    volatile int* q_done = flags + 3 * NBUF;  // drainer -> consumer

    int tid = threadIdx.x;
    if (tid < 4 * NBUF) flags[tid] = 0;
    __syncthreads();

    if (tid == 0) {
        // ------------------- consumer: the serial chain -------------------
        const unsigned c_base0 = smem_u32(c_ring);
        const unsigned q_base0 = smem_u32(q_ring);
        float q0 = 0.f, q1 = 0.f, q2 = 0.f, q3 = 0.f;
        float q4 = 0.f, q5 = 0.f, q6 = 0.f, q7 = 0.f;

        float a0,a1,a2,a3,a4,a5,a6,a7,a8,a9,a10,a11,a12,a13,a14,a15;
        float b0,b1,b2,b3,b4,b5,b6,b7,b8,b9,b10,b11,b12,b13,b14,b15;

        for (int k = 0; k < NCHUNK; k++) {
            int b = k & (NBUF - 1);
            int e = k >> 2;                    // epoch (NBUF == 4)
            while (c_fill[b] < e + 1) {}
            while (q_done[b] < e) {}
            __threadfence_block();

            const unsigned cbase = c_base0 + (unsigned)b * (CH * 64);
            const unsigned qbase = q_base0 + (unsigned)b * (CH * 32);
            const int n = (k == NCHUNK - 1) ? (T_LEN - k * CH) : CH;   // 256 or 64

            // preload step 0 into A
            lds128f(a0,  a1,  a2,  a3,  cbase +  0);
            lds128f(a4,  a5,  a6,  a7,  cbase + 16);
            lds128f(a8,  a9,  a10, a11, cbase + 32);
            lds128f(a12, a13, a14, a15, cbase + 48);

            for (int s = 0; s < n; s += 8) {
                unsigned ca = cbase + (unsigned)s * 64;
                unsigned qa = qbase + (unsigned)s * 32;
                SSTEP(a, b,  64,   0);   // exec s,   load s+1
                SSTEP(b, a, 128,  32);   // exec s+1, load s+2
                SSTEP(a, b, 192,  64);
                SSTEP(b, a, 256,  96);
                SSTEP(a, b, 320, 128);
                SSTEP(b, a, 384, 160);
                SSTEP(a, b, 448, 192);
                SSTEP(b, a, 512, 224);   // loads s+8 -> next iteration's A
                // trailing load reads <=64B past buffer end: lands in the
                // next ring buffer / q ring — allocated smem, values unused.
            }

            __threadfence_block();
            q_fill[b] = e + 1;
            c_done[b] = e + 1;
        }
    } else if (tid < 32) {
        // idle lanes of warp 0 — exit (participate in NO named barriers)
        return;
    } else if (tid < 96) {
        // ------------------- producers: gmem -> c ring -------------------
        int p = tid - 32;   // 0..63
        const float4* src = reinterpret_cast<const float4*>(g_cneg);
        const long total4 = (long)T_LEN * 4;
        for (int k = 0; k < NCHUNK; k++) {
            int b = k & (NBUF - 1);
            int e = k >> 2;
            if (p == 0) { while (c_done[b] < e) {} }
            asm volatile("bar.sync 1, 64;" ::: "memory");
            float4* dst = reinterpret_cast<float4*>(c_ring + (size_t)b * CH * 8);
            long base4 = (long)k * (CH * 4);
#pragma unroll
            for (int j = 0; j < 16; j++) {
                int i = p + j * 64;                       // CH*4 = 1024 float4/chunk
                if (base4 + i < total4) dst[i] = src[base4 + i];
            }
            asm volatile("bar.sync 1, 64;" ::: "memory");   // also drains STS
            if (p == 0) c_fill[b] = e + 1;
        }
    } else {
        // ------------------- drainers: q ring -> det/conf -> out ----------
        int d = tid - 96;  // 0..127
        for (int k = 0; k < NCHUNK; k++) {
            int b = k & (NBUF - 1);
            int e = k >> 2;
            if (d == 0) { while (q_fill[b] < e + 1) {} }
            asm volatile("bar.sync 2, 128;" ::: "memory");
            __threadfence_block();
            const ull* qb = q_ring + (size_t)b * CH * 4;
            int n = (k == NCHUNK - 1) ? (T_LEN - k * CH) : CH;
            for (int s = d; s < n; s += 128) {
                ull u0 = qb[4 * s + 0];
                ull u1 = qb[4 * s + 1];
                ull u2 = qb[4 * s + 2];
                ull u3 = qb[4 * s + 3];
                float q[8] = { lof(u0), hif(u0), lof(u1), hif(u1),
                               lof(u2), hif(u2), lof(u3), hif(u3) };
                float m = q[0];
                int idx = 0;
#pragma unroll
                for (int s2 = 1; s2 < 8; s2++)
                    if (q[s2] < m) { m = q[s2]; idx = s2; }  // first-index argmin
                float sum = 0.0f;
#pragma unroll
                for (int s2 = 0; s2 < 8; s2++)
                    sum += expf(-(q[s2] - m));
                int t = k * CH + s;
                out[t]         = (float)(idx & 1);   // detected_word
                out[T_LEN + t] = 1.0f / sum;         // 2 * confidence_word (== 2/sum16)
            }
            asm volatile("bar.sync 2, 128;" ::: "memory");
            if (d == 0) q_done[b] = e + 1;
        }
    }
}

// ---------------------------------------------------------------------------
// Launch. Inputs: rx[1e6], W1[75], b1[75], W2[1200], b2[16].
// Output: 2*T floats, det first then 2*conf.
// ---------------------------------------------------------------------------
extern "C" void kernel_launch(void* const* d_in, const int* in_sizes, int n_in,
                              void* d_out, int out_size)
{
    const float* rx = (const float*)d_in[0];
    const float* W1 = (const float*)d_in[1];
    const float* b1 = (const float*)d_in[2];
    const float* W2 = (const float*)d_in[3];
    const float* b2 = (const float*)d_in[4];
    float* out = (float*)d_out;

    cudaFuncSetAttribute(pipeline_kernel,
                         cudaFuncAttributeMaxDynamicSharedMemorySize, SMEM_BYTES);

    int blocks = (T_LEN + 255) / 256;
    priors_kernel<<<blocks, 256>>>(rx, W1, b1, W2, b2);
    pipeline_kernel<<<1, 224, SMEM_BYTES>>>(out);
}